// round 17
// baseline (speedup 1.0000x reference)
#include <cuda_runtime.h>
#include <cuda_fp16.h>
#include <math.h>
#include <stdint.h>

// ===========================================================================
// TxtNet, fp16 HMMA.16816 (fp32 accum), cp.async.bulk feeds. ONE kernel.
// R17 = R16 + prep fused as a third CTA role with counter gating:
//   blocks 0..255    : prep (slab-partitioned, shift/mask indexing)
//   blocks 256..1279 : conv CTAs (conv3 first), gate on g_prep==256
//   blocks 1280..1791: slp CTAs, gate chunks on per-conv counters
// Counter reset done by the LAST slp CTA (g_done) -> graph-replay safe.
// Conv: 4 GEMMs K=ntap*320 (zero-pad kstep + dead-col nt3/nt4 cut).
// SLP: 16384 x 1216 x 512 (x5==x3 fold).
// ===========================================================================

#define P_TOT 16384

#define CH_A 0
#define CH_B 16384
#define CH_BUF 36864
#define C_NBUF 3
#define SL_A 0
#define SL_B 16384
#define SL_BUF 32768
#define S_NBUF 3
#define MB_OFF (C_NBUF * CH_BUF)              // 110592
#define FUSED_SMEM (MB_OFF + 128)             // 110720

#define NPREP 256
#define CONV0 256
#define SLP0  1280
#define NGRID 1792

// ------------------------- device scratch (zero-init) ----------------------
__device__ __half g_xc[32 * 5 * 528 * 64];    // [b][kc][row 528 pad][64] sw(row&7)
__device__ __half g_wcc[65 * 320 * 64];       // [slab][oc][64] sw(oc&7)
__device__ __half g_hc[19 * 16384 * 64];      // [kc][pos][64] sw(pos&7)
__device__ __half g_wec[19 * 512 * 64];       // [kc][oc][64] sw(oc&7)
__device__ float g_bconv[1200];
__device__ int   g_prep;                      // prep CTAs completed
__device__ int   g_cnt[4];                    // per-conv completed CTA count
__device__ int   g_done;                      // slp CTAs completed

__constant__ int c_off[13] = {0,  0, 1,  -1, 0, 1,  -3, -2, -1, 0, 1, 2, 3};
__constant__ int c_base[4] = {0, 1, 3, 6};
__constant__ int c_nch[4]  = {5, 10, 15, 35};
__constant__ int c_sb[4]   = {0, 5, 15, 30};
__constant__ int c_sord[19] = {15, 16, 17, 18, 10, 11, 12, 13,
                               5, 6, 7, 8, 0, 1, 2, 3, 14, 9, 4};

// ------------------------- asm helpers -------------------------------------
__device__ __forceinline__ uint32_t smem_u32(const void* p) {
    uint32_t a;
    asm("{ .reg .u64 t; cvta.to.shared.u64 t, %1; cvt.u32.u64 %0, t; }"
        : "=r"(a) : "l"(p));
    return a;
}
#define BULK_G2S(dst, src, bytes, mbar)                                        \
    asm volatile(                                                              \
        "cp.async.bulk.shared::cluster.global.mbarrier::complete_tx::bytes "   \
        "[%0], [%1], %2, [%3];"                                                \
        :: "r"(dst), "l"(src), "r"(bytes), "r"(mbar) : "memory")
#define MBAR_INIT(a, c) \
    asm volatile("mbarrier.init.shared.b64 [%0], %1;" :: "r"(a), "r"(c) : "memory")
#define MBAR_EXPECT_TX(a, b) \
    asm volatile("mbarrier.arrive.expect_tx.shared.b64 _, [%0], %1;" \
                 :: "r"(a), "r"(b) : "memory")
#define MBAR_ARRIVE(a) \
    asm volatile("mbarrier.arrive.shared.b64 _, [%0];" :: "r"(a) : "memory")
#define FENCE_ASYNC() \
    asm volatile("fence.proxy.async.shared::cta;" ::: "memory")
__device__ __forceinline__ void mbar_wait(uint32_t a, uint32_t ph) {
    asm volatile(
        "{\n .reg .pred P;\nW%=:\n"
        " mbarrier.try_wait.parity.acquire.cta.shared::cta.b64 P, [%0], %1, 0x989680;\n"
        " @!P bra W%=;\n}"
        :: "r"(a), "r"(ph) : "memory");
}
#define LDSM4(R, A) \
    asm volatile("ldmatrix.sync.aligned.m8n8.x4.shared.b16 {%0,%1,%2,%3}, [%4];" \
                 : "=r"((R)[0]), "=r"((R)[1]), "=r"((R)[2]), "=r"((R)[3]) : "r"(A))
#define LDSM2(R, A) \
    asm volatile("ldmatrix.sync.aligned.m8n8.x2.shared.b16 {%0,%1}, [%2];" \
                 : "=r"((R)[0]), "=r"((R)[1]) : "r"(A))

__device__ __forceinline__ void mma16816(float* d, const uint32_t* a,
                                         const uint32_t* b) {
    asm volatile(
        "mma.sync.aligned.m16n8k16.row.col.f32.f16.f16.f32 "
        "{%0,%1,%2,%3}, {%4,%5,%6,%7}, {%8,%9}, {%0,%1,%2,%3};"
        : "+f"(d[0]), "+f"(d[1]), "+f"(d[2]), "+f"(d[3])
        : "r"(a[0]), "r"(a[1]), "r"(a[2]), "r"(a[3]), "r"(b[0]), "r"(b[1]));
}

// ------------------------- prep role ---------------------------------------
__device__ void prep_body(int pbid, const float* __restrict__ x,
                          const float* __restrict__ w1, const float* __restrict__ w2,
                          const float* __restrict__ w3, const float* __restrict__ w7,
                          const float* __restrict__ slp_w,
                          const float* __restrict__ b1, const float* __restrict__ b2,
                          const float* __restrict__ b3, const float* __restrict__ b7) {
    const int tid = threadIdx.x;
    if (pbid < 160) {
        // x slab (b, kc): 528 rows x 32 half2  (66*256 = 16896 exact)
        const int b = pbid / 5, kc = pbid - (pbid / 5) * 5;
        const float* xb = x + (size_t)b * 512 * 300;
        __half* dst = g_xc + ((size_t)(b * 5 + kc) * 528) * 64;
#pragma unroll 4
        for (int it = 0; it < 66; ++it) {
            int idx = it * 256 + tid;
            int r = idx >> 5, j = (idx & 31) * 2;
            int rr = r - 8; rr = rr < 0 ? 0 : (rr > 511 ? 511 : rr);
            int c = kc * 64 + j;
            const float* xr = xb + (size_t)rr * 300;
            float v0 = (c < 300) ? xr[c] : 0.f;
            float v1 = (c + 1 < 300) ? xr[c + 1] : 0.f;
            __half2 hv; hv.x = __float2half_rn(v0); hv.y = __float2half_rn(v1);
            int pir = (((j >> 3) ^ (r & 7)) << 3) | (j & 7);
            *(__half2*)(dst + (size_t)r * 64 + pir) = hv;
        }
    } else if (pbid < 225) {
        // conv weight slab s: 320 oc x 32 half2 (40*256 = 10240 exact)
        const int s = pbid - 160;
        int conv = (s < 5) ? 0 : (s < 15) ? 1 : (s < 30) ? 2 : 3;
        int sb = (conv == 0) ? 0 : (conv == 1) ? 5 : (conv == 2) ? 15 : 30;
        int rel = s - sb;
        int tap = rel / 5, kc = rel - (rel / 5) * 5;
        const float* w; int K;
        if (conv == 0)      { w = w1; K = 1; }
        else if (conv == 1) { w = w2; K = 2; }
        else if (conv == 2) { w = w3; K = 3; }
        else                { w = w7; K = 7; }
        __half* dst = g_wcc + (size_t)s * 320 * 64;
#pragma unroll 4
        for (int it = 0; it < 40; ++it) {
            int idx = it * 256 + tid;
            int oc = idx >> 5, j = (idx & 31) * 2;
            int ic = kc * 64 + j;
            float v0 = 0.f, v1 = 0.f;
            if (oc < 300) {
                if (ic < 300)     v0 = w[(oc * 300 + ic) * K + tap];
                if (ic + 1 < 300) v1 = w[(oc * 300 + ic + 1) * K + tap];
            }
            __half2 hv; hv.x = __float2half_rn(v0); hv.y = __float2half_rn(v1);
            int pir = (((j >> 3) ^ (oc & 7)) << 3) | (j & 7);
            *(__half2*)(dst + (size_t)oc * 64 + pir) = hv;
        }
    } else if (pbid < 244) {
        // slp weight slab kc: 512 oc x 32 half2 (64*256 = 16384 exact)
        const int kc = pbid - 225;
        __half* dst = g_wec + (size_t)kc * 512 * 64;
#pragma unroll 4
        for (int it = 0; it < 64; ++it) {
            int idx = it * 256 + tid;
            int oc = idx >> 5, j = (idx & 31) * 2;
            int ic = kc * 64 + j;
            const float* wr = slp_w + (size_t)oc * 1500;
            float v0, v1;
            {
                int i = ic;
                v0 = (i < 600) ? wr[i] : (i < 900) ? wr[i] + wr[i + 300]
                     : (i < 1200) ? wr[i + 300] : 0.f;
                i = ic + 1;
                v1 = (i < 600) ? wr[i] : (i < 900) ? wr[i] + wr[i + 300]
                     : (i < 1200) ? wr[i + 300] : 0.f;
            }
            __half2 hv; hv.x = __float2half_rn(v0); hv.y = __float2half_rn(v1);
            int pir = (((j >> 3) ^ (oc & 7)) << 3) | (j & 7);
            *(__half2*)(dst + (size_t)oc * 64 + pir) = hv;
        }
    } else if (pbid == 244) {
#pragma unroll
        for (int it = 0; it < 5; ++it) {
            int idx = it * 256 + tid;
            if (idx < 1200) {
                int conv = idx / 300, occ = idx - (idx / 300) * 300;
                const float* b = (conv == 0) ? b1 : (conv == 1) ? b2
                                  : (conv == 2) ? b3 : b7;
                g_bconv[idx] = b[occ];
            }
        }
    }
    __threadfence();
    __syncthreads();
    if (tid == 0) atomicAdd(&g_prep, 1);
}

// ------------------------- conv role (BM=128, BN=160, 8 warps) --------------
__device__ void conv_body(char* sm, int bid) {
    const uint32_t smb = smem_u32(sm);
    const uint32_t mbF = smb + MB_OFF;
    const uint32_t mbE = mbF + C_NBUF * 8;
    const int tid = threadIdx.x, lane = tid & 31, wid = tid >> 5;
    const int wm = wid >> 2, wn = wid & 3;               // 2 x 4 warps
    const int quad = lane >> 2, kp2 = (lane & 3) * 2;

    const int conv = 3 - (bid >> 8);                     // conv3 group first
    const int r256 = bid & 255;
    const int oc0  = (r256 & 1) * 160;
    const int pos0 = (r256 >> 1) * 128;
    const int bat = pos0 >> 9, l0 = pos0 & 511;
    const int nc = c_nch[conv];
    const int sbase = c_sb[conv];
    const int tb = c_base[conv];
    const bool cut = (oc0 == 160) && (wn == 3);

    if (tid == 0) {
#pragma unroll
        for (int i = 0; i < C_NBUF; ++i) {
            MBAR_INIT(mbF + i * 8, 1);
            MBAR_INIT(mbE + i * 8, 8);
        }
        FENCE_ASYNC();
    }
    __syncthreads();

    float acc[4][5][4];
#pragma unroll
    for (int mt = 0; mt < 4; ++mt)
#pragma unroll
        for (int nt = 0; nt < 5; ++nt)
#pragma unroll
            for (int e = 0; e < 4; ++e) acc[mt][nt][e] = 0.f;

    auto issue = [&](int ch, int buf) {  // tid0 only
        int tap = ch / 5, kc = ch - tap * 5;
        int dlt = c_off[tb + tap];
        const char* a = (const char*)g_xc +
            ((size_t)((bat * 5 + kc) * 528 + 8 + l0 + dlt)) * 128;
        const char* b = (const char*)g_wcc +
            ((size_t)((sbase + ch) * 320 + oc0)) * 128;
        uint32_t d = smb + buf * CH_BUF;
        uint32_t m = mbF + buf * 8;
        MBAR_EXPECT_TX(m, CH_BUF);
        BULK_G2S(d + CH_A, a, 16384, m);
        BULK_G2S(d + CH_B, b, 20480, m);
    };

    if (tid == 0) {
        while (*((volatile int*)&g_prep) < NPREP) __nanosleep(128);
        issue(0, 0);
        if (nc > 1) issue(1, 1);
        if (nc > 2) issue(2, 2);
    }

    const int hi16 = lane >> 4;
    const int sbB = (lane >> 3) & 1;
    const int rmB = lane & 7;
    const uint32_t aRow  = (uint32_t)(wm * 64 + (lane & 15)) * 128;
    const uint32_t bRow  = (uint32_t)(wn * 40 + (lane & 7) +
                                      ((lane >> 4) & 1) * 8) * 128;
    const uint32_t bRow2 = (uint32_t)(wn * 40 + 32 + (lane & 7)) * 128;

    int buf = 0, ph = 0;
    for (int ch = 0; ch < nc; ++ch) {
        mbar_wait(mbF + buf * 8, ph);
        int tap = ch / 5;
        int kcl = ch - tap * 5;
        int adj = (8 + c_off[tb + tap]) & 7;
        int rmA = ((lane & 15) + adj) & 7;
        const uint32_t Ab = smb + buf * CH_BUF + CH_A;
        const uint32_t Bb = smb + buf * CH_BUF + CH_B;

        auto kstep = [&](int kk) {
            const uint32_t sA = (uint32_t)(((kk * 2 + hi16) ^ rmA) << 4);
            const uint32_t sB = (uint32_t)(((kk * 2 + sbB) ^ rmB) << 4);
            uint32_t ah[4][4];
#pragma unroll
            for (int mt = 0; mt < 4; ++mt)
                LDSM4(ah[mt], Ab + aRow + mt * 2048 + sA);
            uint32_t bh4[4];
            LDSM4(bh4, Bb + bRow + sB);
#pragma unroll
            for (int mt = 0; mt < 4; ++mt) {
                mma16816(acc[mt][0], ah[mt], bh4);
                mma16816(acc[mt][1], ah[mt], bh4 + 2);
            }
            LDSM4(bh4, Bb + bRow + 2048 + sB);
#pragma unroll
            for (int mt = 0; mt < 4; ++mt)
                mma16816(acc[mt][2], ah[mt], bh4);
            if (!cut) {
#pragma unroll
                for (int mt = 0; mt < 4; ++mt)
                    mma16816(acc[mt][3], ah[mt], bh4 + 2);   // cols 304..311 dead
                uint32_t bh2[2];
                LDSM2(bh2, Bb + bRow2 + sB);
#pragma unroll
                for (int mt = 0; mt < 4; ++mt)
                    mma16816(acc[mt][4], ah[mt], bh2);
            }
        };

        kstep(0);
        kstep(1);
        kstep(2);
        if (kcl != 4) kstep(3);          // ic 304..319 zero pad: skip
        __syncwarp();
        if (lane == 0) MBAR_ARRIVE(mbE + buf * 8);
        if (tid == 0 && ch + C_NBUF < nc) {
            mbar_wait(mbE + buf * 8, ph);
            issue(ch + C_NBUF, buf);
        }
        if (++buf == C_NBUF) { buf = 0; ph ^= 1; }
    }

    // epilogue: tanh(acc + bias) -> chunked+swizzled fp16 h
#pragma unroll
    for (int mt = 0; mt < 4; ++mt) {
        int r0 = pos0 + wm * 64 + mt * 16 + quad;
#pragma unroll
        for (int nt = 0; nt < 5; ++nt) {
            int col = oc0 + wn * 40 + nt * 8 + kp2;
            if (col >= 300) continue;
            int gc = conv * 300 + col;
            int kc = gc >> 6, j = gc & 63;
            float bi0 = g_bconv[gc], bi1 = g_bconv[gc + 1];
#pragma unroll
            for (int half = 0; half < 2; ++half) {
                int r = r0 + half * 8;
                __half2 hv;
                hv.x = __float2half_rn(tanhf(acc[mt][nt][half * 2 + 0] + bi0));
                hv.y = __float2half_rn(tanhf(acc[mt][nt][half * 2 + 1] + bi1));
                int pir = (((j >> 3) ^ (r & 7)) << 3) | (j & 7);
                *(__half2*)(g_hc + ((size_t)kc * 16384 + r) * 64 + pir) = hv;
            }
        }
    }

    __threadfence();
    __syncthreads();
    if (tid == 0) atomicAdd(&g_cnt[conv], 1);
}

// ------------------------- slp role (BM=128, BN=128, 8 warps) ---------------
__device__ void slp_body(char* sm, int bid,
                         const float* __restrict__ slp_b,
                         float* __restrict__ out) {
    const uint32_t smb = smem_u32(sm);
    const uint32_t mbF = smb + MB_OFF;
    const uint32_t mbE = mbF + S_NBUF * 8;
    const int tid = threadIdx.x, lane = tid & 31, wid = tid >> 5;
    const int wm = wid >> 2, wn = wid & 3;
    const int quad = lane >> 2, kp2 = (lane & 3) * 2;
    const int sbid = bid;
    const int oc0  = (sbid & 3) * 128;
    const int pos0 = (sbid >> 2) * 128;
    const int nc = 19;
    const int rmA = lane & 7;

    if (tid == 0) {
#pragma unroll
        for (int i = 0; i < S_NBUF; ++i) {
            MBAR_INIT(mbF + i * 8, 1);
            MBAR_INIT(mbE + i * 8, 8);
        }
        FENCE_ASYNC();
    }
    __syncthreads();

    float acc[4][4][4];
#pragma unroll
    for (int mt = 0; mt < 4; ++mt)
#pragma unroll
        for (int nt = 0; nt < 4; ++nt)
#pragma unroll
            for (int e = 0; e < 4; ++e) acc[mt][nt][e] = 0.f;

    auto gate = [&](int ch) {            // tid0 only
        int mask = (ch < 4) ? 1 : (ch == 4) ? 3 : (ch < 9) ? 2
                   : (ch == 9) ? 6 : (ch < 14) ? 4 : (ch == 14) ? 12 : 8;
#pragma unroll
        for (int c = 0; c < 4; ++c)
            if ((mask >> c) & 1)
                while (*((volatile int*)&g_cnt[c]) < 256) __nanosleep(256);
    };

    auto issue = [&](int i, int buf) {   // tid0 only
        int ch = c_sord[i];
        gate(ch);
        const char* a = (const char*)g_hc + ((size_t)ch * 16384 + pos0) * 128;
        const char* b = (const char*)g_wec + ((size_t)ch * 512 + oc0) * 128;
        uint32_t d = smb + buf * SL_BUF;
        uint32_t m = mbF + buf * 8;
        MBAR_EXPECT_TX(m, SL_BUF);
        BULK_G2S(d + SL_A, a, 16384, m);
        BULK_G2S(d + SL_B, b, 16384, m);
    };

    if (tid == 0) { issue(0, 0); issue(1, 1); issue(2, 2); }

    const int hi16 = lane >> 4;
    const int sbB = (lane >> 3) & 1;
    const int rmB = lane & 7;
    const uint32_t aRow  = (uint32_t)(wm * 64 + (lane & 15)) * 128;
    const uint32_t bRow  = (uint32_t)(wn * 32 + (lane & 7) +
                                      ((lane >> 4) & 1) * 8) * 128;

    int buf = 0, ph = 0;
    for (int i = 0; i < nc; ++i) {
        int ch = c_sord[i];
        mbar_wait(mbF + buf * 8, (i / S_NBUF) & 1);
        const uint32_t Ab = smb + buf * SL_BUF + SL_A;
        const uint32_t Bb = smb + buf * SL_BUF + SL_B;

        auto kstep = [&](int kk) {
            const uint32_t sA = (uint32_t)(((kk * 2 + hi16) ^ rmA) << 4);
            const uint32_t sB = (uint32_t)(((kk * 2 + sbB) ^ rmB) << 4);
            uint32_t ah[4][4];
#pragma unroll
            for (int mt = 0; mt < 4; ++mt)
                LDSM4(ah[mt], Ab + aRow + mt * 2048 + sA);
#pragma unroll
            for (int p = 0; p < 2; ++p) {
                uint32_t bh[4];
                LDSM4(bh, Bb + bRow + p * 2048 + sB);
#pragma unroll
                for (int q = 0; q < 2; ++q)
#pragma unroll
                    for (int mt = 0; mt < 4; ++mt)
                        mma16816(acc[mt][p * 2 + q], ah[mt], bh + q * 2);
            }
        };

        kstep(0);
        kstep(1);
        kstep(2);
        if (ch != 18) kstep(3);          // ic 1200..1215 zero pad: skip
        __syncwarp();
        if (lane == 0) MBAR_ARRIVE(mbE + buf * 8);
        if (tid == 0 && i + S_NBUF < nc) {
            mbar_wait(mbE + buf * 8, ph);
            issue(i + S_NBUF, buf);
        }
        if (++buf == S_NBUF) { buf = 0; ph ^= 1; }
    }

#pragma unroll
    for (int mt = 0; mt < 4; ++mt) {
        int r0 = pos0 + wm * 64 + mt * 16 + quad;
#pragma unroll
        for (int nt = 0; nt < 4; ++nt) {
            int col = oc0 + wn * 32 + nt * 8 + kp2;
            float bi0 = slp_b[col], bi1 = slp_b[col + 1];
#pragma unroll
            for (int half = 0; half < 2; ++half) {
                int r = r0 + half * 8;
                float2 v;
                v.x = tanhf(acc[mt][nt][half * 2 + 0] + bi0);
                v.y = tanhf(acc[mt][nt][half * 2 + 1] + bi1);
                *(float2*)(out + (size_t)r * 512 + col) = v;
            }
        }
    }

    // last-finisher resets all counters (graph-replay safe)
    __threadfence();
    __syncthreads();
    if (tid == 0) {
        int d = atomicAdd(&g_done, 1);
        if (d == 511) {
            g_prep = 0;
            g_cnt[0] = 0; g_cnt[1] = 0; g_cnt[2] = 0; g_cnt[3] = 0;
            g_done = 0;
            __threadfence();
        }
    }
}

// ------------------------- fused kernel ------------------------------------
__global__ __launch_bounds__(256, 2)
void fused_kernel(const float* __restrict__ x,
                  const float* __restrict__ w1, const float* __restrict__ w2,
                  const float* __restrict__ w3, const float* __restrict__ w7,
                  const float* __restrict__ slp_w,
                  const float* __restrict__ b1, const float* __restrict__ b2,
                  const float* __restrict__ b3, const float* __restrict__ b7,
                  const float* __restrict__ slp_b, float* __restrict__ out) {
    extern __shared__ char sm[];
    const int bid = blockIdx.x;
    if (bid < NPREP)      prep_body(bid, x, w1, w2, w3, w7, slp_w,
                                    b1, b2, b3, b7);
    else if (bid < SLP0)  conv_body(sm, bid - CONV0);
    else                  slp_body(sm, bid - SLP0, slp_b, out);
}

// ------------------------- launch ------------------------------------------
extern "C" void kernel_launch(void* const* d_in, const int* in_sizes, int n_in,
                              void* d_out, int out_size) {
    const float* x     = (const float*)d_in[0];
    const float* w1    = (const float*)d_in[1];
    const float* b1    = (const float*)d_in[2];
    const float* w2    = (const float*)d_in[3];
    const float* b2    = (const float*)d_in[4];
    const float* w3    = (const float*)d_in[5];
    const float* b3    = (const float*)d_in[6];
    const float* w7    = (const float*)d_in[7];
    const float* b7    = (const float*)d_in[8];
    const float* slp_w = (const float*)d_in[9];
    const float* slp_b = (const float*)d_in[10];
    float* out = (float*)d_out;

    cudaFuncSetAttribute(fused_kernel,
                         cudaFuncAttributeMaxDynamicSharedMemorySize, FUSED_SMEM);

    fused_kernel<<<NGRID, 256, FUSED_SMEM>>>(x, w1, w2, w3, w7, slp_w,
                                             b1, b2, b3, b7, slp_b, out);
}